// round 3
// baseline (speedup 1.0000x reference)
#include <cuda_runtime.h>
#include <cuda_bf16.h>
#include <cstdint>

#define BATCH 128
#define SEQ   512
#define EMB   300
#define HID   128
#define G4H   512          // 4*HID
#define NTAG  12
#define SOS_T 3
#define EOS_T 4
#define NEGV  (-10000.0f)

#define GM (BATCH*SEQ)     // 65536 tokens

// ---------------- scratch (device globals; no allocation allowed) ----------------
__device__ float g_gix[2ull * GM * G4H];          // [dir][m][512]  (268 MB)
__device__ float g_h  [2ull * GM * HID];          // [dir][m][128]  (67 MB)
__device__ float g_y  [(size_t)GM * NTAG];        // [m][12]        (3 MB)

// ---------------- fast activations ----------------
__device__ __forceinline__ float sigf(float x) {
    return 1.0f / (1.0f + __expf(-x));
}
__device__ __forceinline__ float tanhfast(float x) {
    // tanh(x) = 1 - 2/(exp(2x)+1); handles +/-inf of expf correctly
    return 1.0f - 2.0f / (__expf(2.0f * x) + 1.0f);
}

// =====================================================================
// K1: input projection  gix[dir][m][j] = sum_k embed[x[m]][k]*Wih[j][k] + b[j]
//   grid: (N/128=4, M/128=512, 2 dirs), 256 threads, BM=BN=128, BK=20
// =====================================================================
__global__ void __launch_bounds__(256) k_input_gemm(
    const int* __restrict__ x, const float* __restrict__ embed,
    const float* __restrict__ Wf, const float* __restrict__ bf,
    const float* __restrict__ Wb, const float* __restrict__ bb)
{
    const int dir = blockIdx.z;
    const float* __restrict__ W    = dir ? Wb : Wf;
    const float* __restrict__ bias = dir ? bb : bf;
    float* __restrict__ out = g_gix + (size_t)dir * GM * G4H;

    __shared__ float As[20][132];   // [k][m], 132 floats/row = 528B (16B multiple)
    __shared__ float Bs[20][132];   // [k][n]

    const int tid = threadIdx.x;
    const int m0 = blockIdx.y * 128;
    const int n0 = blockIdx.x * 128;

    const int lrow = tid >> 1;          // 0..127
    const int lk0  = (tid & 1) * 10;    // 0 or 10

    const int tok = x[m0 + lrow];
    const float* __restrict__ arow = embed + (size_t)tok * EMB;
    const float* __restrict__ brow = W + (size_t)(n0 + lrow) * EMB;

    const int tm = (tid >> 4) * 8;      // 0..120
    const int tn = (tid & 15) * 8;

    float acc[8][8];
    #pragma unroll
    for (int i = 0; i < 8; i++)
        #pragma unroll
        for (int j = 0; j < 8; j++) acc[i][j] = 0.0f;

    for (int k0 = 0; k0 < EMB; k0 += 20) {
        #pragma unroll
        for (int q = 0; q < 10; q++) {
            As[lk0 + q][lrow] = arow[k0 + lk0 + q];
            Bs[lk0 + q][lrow] = brow[k0 + lk0 + q];
        }
        __syncthreads();
        #pragma unroll
        for (int kk = 0; kk < 20; kk++) {
            float a[8], b[8];
            *(float4*)&a[0] = *(const float4*)&As[kk][tm];
            *(float4*)&a[4] = *(const float4*)&As[kk][tm + 4];
            *(float4*)&b[0] = *(const float4*)&Bs[kk][tn];
            *(float4*)&b[4] = *(const float4*)&Bs[kk][tn + 4];
            #pragma unroll
            for (int i = 0; i < 8; i++)
                #pragma unroll
                for (int j = 0; j < 8; j++)
                    acc[i][j] += a[i] * b[j];
        }
        __syncthreads();
    }

    #pragma unroll
    for (int i = 0; i < 8; i++) {
        float* __restrict__ orow = out + (size_t)(m0 + tm + i) * G4H + n0 + tn;
        #pragma unroll
        for (int j = 0; j < 8; j++)
            orow[j] = acc[i][j] + bias[n0 + tn + j];
    }
}

// =====================================================================
// K2: LSTM recurrence. grid 64 = 2 dirs x 16 groups of 4 batch, 512 threads.
// thread j owns gate row j ([i|f|g|o] x 128 units); h state in smem [k][nb].
// =====================================================================
__global__ void __launch_bounds__(512) k_lstm(
    const float* __restrict__ Whh_f, const float* __restrict__ Whh_b)
{
    const int dir = blockIdx.x >> 5;          // 0..1
    const int b0  = (blockIdx.x & 31) * 4;    // batch base
    const float* __restrict__ Whh = dir ? Whh_b : Whh_f;

    const int j = threadIdx.x;                // gate row 0..511

    __shared__ float hs[128][4];              // h[k][nb]
    __shared__ float gs[4][128][4];           // gates[gt][k][nb]

    if (j < 128) {
        *(float4*)&hs[j][0] = make_float4(0.f, 0.f, 0.f, 0.f);
    }
    float c0 = 0.f, c1 = 0.f, c2 = 0.f, c3 = 0.f;
    __syncthreads();

    const float4* __restrict__ wrow = (const float4*)(Whh + (size_t)j * HID);
    const float* __restrict__ gixd = g_gix + (size_t)dir * GM * G4H;
    float* __restrict__ hout = g_h + (size_t)dir * GM * HID;

    for (int t = 0; t < SEQ; t++) {
        const int tt = dir ? (SEQ - 1 - t) : t;

        float a0 = gixd[((size_t)(b0 + 0) * SEQ + tt) * G4H + j];
        float a1 = gixd[((size_t)(b0 + 1) * SEQ + tt) * G4H + j];
        float a2 = gixd[((size_t)(b0 + 2) * SEQ + tt) * G4H + j];
        float a3 = gixd[((size_t)(b0 + 3) * SEQ + tt) * G4H + j];

        #pragma unroll
        for (int kk = 0; kk < 32; kk++) {
            const float4 w = wrow[kk];
            float4 h;
            h = *(const float4*)&hs[kk * 4 + 0][0];
            a0 += w.x * h.x; a1 += w.x * h.y; a2 += w.x * h.z; a3 += w.x * h.w;
            h = *(const float4*)&hs[kk * 4 + 1][0];
            a0 += w.y * h.x; a1 += w.y * h.y; a2 += w.y * h.z; a3 += w.y * h.w;
            h = *(const float4*)&hs[kk * 4 + 2][0];
            a0 += w.z * h.x; a1 += w.z * h.y; a2 += w.z * h.z; a3 += w.z * h.w;
            h = *(const float4*)&hs[kk * 4 + 3][0];
            a0 += w.w * h.x; a1 += w.w * h.y; a2 += w.w * h.z; a3 += w.w * h.w;
        }

        const int gt = j >> 7, k = j & 127;
        *(float4*)&gs[gt][k][0] = make_float4(a0, a1, a2, a3);
        __syncthreads();

        if (j < 128) {
            const float4 gi = *(const float4*)&gs[0][j][0];
            const float4 gf = *(const float4*)&gs[1][j][0];
            const float4 gg = *(const float4*)&gs[2][j][0];
            const float4 go = *(const float4*)&gs[3][j][0];

            c0 = sigf(gf.x) * c0 + sigf(gi.x) * tanhfast(gg.x);
            c1 = sigf(gf.y) * c1 + sigf(gi.y) * tanhfast(gg.y);
            c2 = sigf(gf.z) * c2 + sigf(gi.z) * tanhfast(gg.z);
            c3 = sigf(gf.w) * c3 + sigf(gi.w) * tanhfast(gg.w);

            const float h0 = sigf(go.x) * tanhfast(c0);
            const float h1 = sigf(go.y) * tanhfast(c1);
            const float h2 = sigf(go.z) * tanhfast(c2);
            const float h3 = sigf(go.w) * tanhfast(c3);

            *(float4*)&hs[j][0] = make_float4(h0, h1, h2, h3);

            hout[((size_t)(b0 + 0) * SEQ + tt) * HID + j] = h0;
            hout[((size_t)(b0 + 1) * SEQ + tt) * HID + j] = h1;
            hout[((size_t)(b0 + 2) * SEQ + tt) * HID + j] = h2;
            hout[((size_t)(b0 + 3) * SEQ + tt) * HID + j] = h3;
        }
        __syncthreads();
    }
}

// =====================================================================
// K3: output projection  y[m][tag] = [hf|hb] . Wout[tag] + bout[tag]
//   grid 2048 blocks x 384 threads; each block 32 m-values.
// =====================================================================
__global__ void __launch_bounds__(384) k_proj(
    const float* __restrict__ Wout, const float* __restrict__ bout)
{
    __shared__ float hbuf[32][260];
    __shared__ float Ws[12][260];
    __shared__ float bs[12];

    const int tid = threadIdx.x;
    const int m0 = blockIdx.x * 32;

    for (int idx = tid; idx < 12 * 256; idx += 384) {
        Ws[idx >> 8][idx & 255] = Wout[idx];
    }
    if (tid < 12) bs[tid] = bout[tid];

    for (int idx = tid; idx < 32 * 128; idx += 384) {
        const int i = idx >> 7, k = idx & 127;
        hbuf[i][k]       = g_h[(size_t)(m0 + i) * HID + k];
        hbuf[i][128 + k] = g_h[(size_t)GM * HID + (size_t)(m0 + i) * HID + k];
    }
    __syncthreads();

    const int i = tid / 12, tag = tid % 12;   // 384 = 32*12
    float acc = bs[tag];
    #pragma unroll 8
    for (int k = 0; k < 256; k++)
        acc += hbuf[i][k] * Ws[tag][k];
    g_y[(size_t)(m0 + i) * NTAG + tag] = acc;
}

// =====================================================================
// K4: CRF forward (partition Z) + gold path score. 1 warp per batch elem.
// =====================================================================
__global__ void __launch_bounds__(32) k_crf(
    const int* __restrict__ y0, const float* __restrict__ trans,
    float* __restrict__ out)
{
    const int b = blockIdx.x;
    const int lane = threadIdx.x;

    __shared__ float tr[144];
    __shared__ float sc[12];

    for (int i = lane; i < 144; i += 32) tr[i] = trans[i];
    if (lane < 12) sc[lane] = (lane == SOS_T) ? 0.0f : NEGV;
    __syncwarp();

    const float* __restrict__ yb = g_y + (size_t)b * SEQ * NTAG;

    for (int t = 0; t < SEQ; t++) {
        float nv = 0.f;
        if (lane < 12) {
            float mx = -3.0e38f;
            #pragma unroll
            for (int jj = 0; jj < 12; jj++)
                mx = fmaxf(mx, sc[jj] + tr[lane * 12 + jj]);
            float s = 0.f;
            #pragma unroll
            for (int jj = 0; jj < 12; jj++)
                s += __expf(sc[jj] + tr[lane * 12 + jj] - mx);
            nv = mx + __logf(s) + yb[t * NTAG + lane];
        }
        __syncwarp();
        if (lane < 12) sc[lane] = nv;
        __syncwarp();
    }

    // gold path: emissions + transitions along y0 path
    const int* __restrict__ y0b = y0 + b * SEQ;
    float emit = 0.f, trs = 0.f;
    for (int t = lane; t < SEQ; t += 32) {
        const int cur = y0b[t];
        const int prev = (t == 0) ? SOS_T : y0b[t - 1];
        emit += yb[t * NTAG + cur];
        trs  += tr[cur * 12 + prev];
    }
    #pragma unroll
    for (int off = 16; off > 0; off >>= 1) {
        emit += __shfl_down_sync(0xffffffffu, emit, off);
        trs  += __shfl_down_sync(0xffffffffu, trs,  off);
    }

    if (lane == 0) {
        float mx = -3.0e38f;
        #pragma unroll
        for (int jj = 0; jj < 12; jj++)
            mx = fmaxf(mx, sc[jj] + tr[EOS_T * 12 + jj]);
        float s = 0.f;
        #pragma unroll
        for (int jj = 0; jj < 12; jj++)
            s += __expf(sc[jj] + tr[EOS_T * 12 + jj] - mx);
        const float Z = mx + __logf(s);
        const float gold = emit + trs + tr[EOS_T * 12 + y0b[SEQ - 1]];
        out[b] = Z - gold;
    }
}

// =====================================================================
extern "C" void kernel_launch(void* const* d_in, const int* in_sizes, int n_in,
                              void* d_out, int out_size)
{
    (void)in_sizes; (void)n_in; (void)out_size;
    const int*   x     = (const int*)  d_in[0];
    const int*   y0    = (const int*)  d_in[1];
    const float* embed = (const float*)d_in[2];
    const float* Wih_f = (const float*)d_in[3];
    const float* Whh_f = (const float*)d_in[4];
    const float* b_f   = (const float*)d_in[5];
    const float* Wih_b = (const float*)d_in[6];
    const float* Whh_b = (const float*)d_in[7];
    const float* b_b   = (const float*)d_in[8];
    const float* Wout  = (const float*)d_in[9];
    const float* bout  = (const float*)d_in[10];
    const float* trans = (const float*)d_in[11];
    float* out = (float*)d_out;

    dim3 g1(4, 512, 2);
    k_input_gemm<<<g1, 256>>>(x, embed, Wih_f, b_f, Wih_b, b_b);
    k_lstm<<<64, 512>>>(Whh_f, Whh_b);
    k_proj<<<2048, 384>>>(Wout, bout);
    k_crf<<<128, 32>>>(y0, trans, out);
}

// round 4
// speedup vs baseline: 1.0457x; 1.0457x over previous
#include <cuda_runtime.h>
#include <cuda_bf16.h>
#include <cstdint>

#define BATCH 128
#define SEQ   512
#define EMB   300
#define HID   128
#define G4H   512          // 4*HID
#define NTAG  12
#define SOS_T 3
#define EOS_T 4
#define NEGV  (-10000.0f)

#define GM (BATCH*SEQ)     // 65536 tokens

typedef unsigned long long ull;

// ---------------- scratch (device globals; no allocation allowed) ----------------
__device__ float  g_gix[2ull * GM * G4H];          // [dir][m][512]  (268 MB)
__device__ float  g_h  [2ull * GM * HID];          // [dir][m][128]  (67 MB)
__device__ float  g_y  [(size_t)GM * NTAG];        // [m][12]        (3 MB)
__device__ float4 g_wt [2][32][512];               // transposed Whh: [dir][kk][j] = Whh[j][4kk..4kk+3]

// ---------------- f32x2 packed helpers ----------------
__device__ __forceinline__ ull fma2(ull a, ull b, ull c) {
    ull d;
    asm("fma.rn.f32x2 %0, %1, %2, %3;" : "=l"(d) : "l"(a), "l"(b), "l"(c));
    return d;
}
__device__ __forceinline__ ull dup2(float a) {
    ull d;
    asm("mov.b64 %0, {%1, %1};" : "=l"(d) : "f"(a));
    return d;
}
__device__ __forceinline__ float2 unpk(ull v) {
    float2 r;
    asm("mov.b64 {%0, %1}, %2;" : "=f"(r.x), "=f"(r.y) : "l"(v));
    return r;
}

// ---------------- fast activations ----------------
__device__ __forceinline__ float sigf(float x) {
    return 1.0f / (1.0f + __expf(-x));
}
__device__ __forceinline__ float tanhfast(float x) {
    return 1.0f - 2.0f / (__expf(2.0f * x) + 1.0f);
}

// =====================================================================
// K0: transpose Whh into g_wt for coalesced recurrence loads.
//   block (kk=bIdx.x, dir=bIdx.y), 512 threads: g_wt[dir][kk][j] = row j chunk kk
// =====================================================================
__global__ void __launch_bounds__(512) k_wt(
    const float* __restrict__ Whh_f, const float* __restrict__ Whh_b)
{
    const float* __restrict__ W = blockIdx.y ? Whh_b : Whh_f;
    const int kk = blockIdx.x;
    const int j  = threadIdx.x;
    g_wt[blockIdx.y][kk][j] = ((const float4*)(W + (size_t)j * HID))[kk];
}

// =====================================================================
// K1: input projection  gix[dir][m][j] = sum_k embed[x[m]][k]*Wih[j][k] + b[j]
//   grid: (4, 512, 2), 256 threads, BM=BN=128, BK=20.  f32x2 accumulators (n-paired).
// =====================================================================
__global__ void __launch_bounds__(256) k_input_gemm(
    const int* __restrict__ x, const float* __restrict__ embed,
    const float* __restrict__ Wf, const float* __restrict__ bf,
    const float* __restrict__ Wb, const float* __restrict__ bb)
{
    const int dir = blockIdx.z;
    const float* __restrict__ W    = dir ? Wb : Wf;
    const float* __restrict__ bias = dir ? bb : bf;
    float* __restrict__ out = g_gix + (size_t)dir * GM * G4H;

    __shared__ float As[20][132];   // [k][m]
    __shared__ float Bs[20][132];   // [k][n]

    const int tid = threadIdx.x;
    const int m0 = blockIdx.y * 128;
    const int n0 = blockIdx.x * 128;

    const int lrow = tid >> 1;          // 0..127
    const int lk0  = (tid & 1) * 10;    // 0 or 10

    const int tok = x[m0 + lrow];
    // rows are 1200B (16B-multiple) strided; +lk0 keeps 8B alignment -> float2 loads legal
    const float* __restrict__ arow = embed + (size_t)tok * EMB;
    const float* __restrict__ brow = W + (size_t)(n0 + lrow) * EMB;

    const int tm = (tid >> 4) * 8;      // 0..120
    const int tn = (tid & 15) * 8;

    ull acc2[8][4];                     // [i][j-pair]
    #pragma unroll
    for (int i = 0; i < 8; i++)
        #pragma unroll
        for (int jp = 0; jp < 4; jp++) acc2[i][jp] = 0ull;

    for (int k0 = 0; k0 < EMB; k0 += 20) {
        #pragma unroll
        for (int q = 0; q < 5; q++) {
            const float2 av = *(const float2*)(arow + k0 + lk0 + 2 * q);
            const float2 bv = *(const float2*)(brow + k0 + lk0 + 2 * q);
            As[lk0 + 2 * q    ][lrow] = av.x;
            As[lk0 + 2 * q + 1][lrow] = av.y;
            Bs[lk0 + 2 * q    ][lrow] = bv.x;
            Bs[lk0 + 2 * q + 1][lrow] = bv.y;
        }
        __syncthreads();
        #pragma unroll
        for (int kk = 0; kk < 20; kk++) {
            float a[8];
            *(float4*)&a[0] = *(const float4*)&As[kk][tm];
            *(float4*)&a[4] = *(const float4*)&As[kk][tm + 4];
            ulonglong2 b01 = *(const ulonglong2*)&Bs[kk][tn];
            ulonglong2 b23 = *(const ulonglong2*)&Bs[kk][tn + 4];
            #pragma unroll
            for (int i = 0; i < 8; i++) {
                const ull ad = dup2(a[i]);
                acc2[i][0] = fma2(ad, b01.x, acc2[i][0]);
                acc2[i][1] = fma2(ad, b01.y, acc2[i][1]);
                acc2[i][2] = fma2(ad, b23.x, acc2[i][2]);
                acc2[i][3] = fma2(ad, b23.y, acc2[i][3]);
            }
        }
        __syncthreads();
    }

    const float4 bias0 = *(const float4*)&bias[n0 + tn];
    const float4 bias1 = *(const float4*)&bias[n0 + tn + 4];
    #pragma unroll
    for (int i = 0; i < 8; i++) {
        float* __restrict__ orow = out + (size_t)(m0 + tm + i) * G4H + n0 + tn;
        const float2 v0 = unpk(acc2[i][0]);
        const float2 v1 = unpk(acc2[i][1]);
        const float2 v2 = unpk(acc2[i][2]);
        const float2 v3 = unpk(acc2[i][3]);
        float4 o0 = make_float4(v0.x + bias0.x, v0.y + bias0.y, v1.x + bias0.z, v1.y + bias0.w);
        float4 o1 = make_float4(v2.x + bias1.x, v2.y + bias1.y, v3.x + bias1.z, v3.y + bias1.w);
        *(float4*)&orow[0] = o0;
        *(float4*)&orow[4] = o1;
    }
}

// =====================================================================
// K2: LSTM recurrence. 64 blocks = 2 dirs x 16 groups of 4 batch, 512 threads.
// thread j owns gate row j; h state in smem [b][k]; f32x2 k-paired accumulators.
// =====================================================================
__global__ void __launch_bounds__(512) k_lstm()
{
    const int dir = blockIdx.x >> 5;          // 0..1
    const int b0  = (blockIdx.x & 31) * 4;    // batch base

    const int j = threadIdx.x;                // gate row 0..511

    __shared__ float hs[4][HID];              // h[b][k]
    __shared__ float gs[4][G4H];              // gates[b][j]

    if (j < 128) {
        hs[0][j] = 0.f; hs[1][j] = 0.f; hs[2][j] = 0.f; hs[3][j] = 0.f;
    }
    float c0 = 0.f, c1 = 0.f, c2 = 0.f, c3 = 0.f;
    __syncthreads();

    const ulonglong2* __restrict__ wt = (const ulonglong2*)&g_wt[dir][0][j];  // stride 512 float4
    const float* __restrict__ gixd = g_gix + (size_t)dir * GM * G4H;
    float* __restrict__ hout = g_h + (size_t)dir * GM * HID;

    for (int t = 0; t < SEQ; t++) {
        const int tt = dir ? (SEQ - 1 - t) : t;

        // issue gix loads early; consumed only at the end of the k-loop
        const float gb0 = gixd[((size_t)(b0 + 0) * SEQ + tt) * G4H + j];
        const float gb1 = gixd[((size_t)(b0 + 1) * SEQ + tt) * G4H + j];
        const float gb2 = gixd[((size_t)(b0 + 2) * SEQ + tt) * G4H + j];
        const float gb3 = gixd[((size_t)(b0 + 3) * SEQ + tt) * G4H + j];

        ull ac0 = 0ull, ac1 = 0ull, ac2 = 0ull, ac3 = 0ull;   // (even-k, odd-k) partials

        #pragma unroll
        for (int kk = 0; kk < 32; kk++) {
            const ulonglong2 w = wt[(size_t)kk * 512];         // coalesced across warp
            const ulonglong2 h0 = *(const ulonglong2*)&hs[0][kk * 4];
            const ulonglong2 h1 = *(const ulonglong2*)&hs[1][kk * 4];
            const ulonglong2 h2 = *(const ulonglong2*)&hs[2][kk * 4];
            const ulonglong2 h3 = *(const ulonglong2*)&hs[3][kk * 4];
            ac0 = fma2(w.x, h0.x, ac0); ac0 = fma2(w.y, h0.y, ac0);
            ac1 = fma2(w.x, h1.x, ac1); ac1 = fma2(w.y, h1.y, ac1);
            ac2 = fma2(w.x, h2.x, ac2); ac2 = fma2(w.y, h2.y, ac2);
            ac3 = fma2(w.x, h3.x, ac3); ac3 = fma2(w.y, h3.y, ac3);
        }

        {
            const float2 p0 = unpk(ac0), p1 = unpk(ac1), p2 = unpk(ac2), p3 = unpk(ac3);
            gs[0][j] = p0.x + p0.y + gb0;
            gs[1][j] = p1.x + p1.y + gb1;
            gs[2][j] = p2.x + p2.y + gb2;
            gs[3][j] = p3.x + p3.y + gb3;
        }
        __syncthreads();

        if (j < 128) {
            const int u = j;
            #pragma unroll
            for (int b = 0; b < 4; b++) {
                const float gi = gs[b][u];
                const float gf = gs[b][HID + u];
                const float gg = gs[b][2 * HID + u];
                const float go = gs[b][3 * HID + u];
                float& c = (b == 0) ? c0 : (b == 1) ? c1 : (b == 2) ? c2 : c3;
                c = sigf(gf) * c + sigf(gi) * tanhfast(gg);
                const float h = sigf(go) * tanhfast(c);
                hs[b][u] = h;
                hout[((size_t)(b0 + b) * SEQ + tt) * HID + u] = h;
            }
        }
        __syncthreads();
    }
}

// =====================================================================
// K3: output projection  y[m][tag] = [hf|hb] . Wout[tag] + bout[tag]
// =====================================================================
__global__ void __launch_bounds__(384) k_proj(
    const float* __restrict__ Wout, const float* __restrict__ bout)
{
    __shared__ float hbuf[32][260];
    __shared__ float Ws[12][260];
    __shared__ float bs[12];

    const int tid = threadIdx.x;
    const int m0 = blockIdx.x * 32;

    for (int idx = tid; idx < 12 * 256; idx += 384) {
        Ws[idx >> 8][idx & 255] = Wout[idx];
    }
    if (tid < 12) bs[tid] = bout[tid];

    for (int idx = tid; idx < 32 * 128; idx += 384) {
        const int i = idx >> 7, k = idx & 127;
        hbuf[i][k]       = g_h[(size_t)(m0 + i) * HID + k];
        hbuf[i][128 + k] = g_h[(size_t)GM * HID + (size_t)(m0 + i) * HID + k];
    }
    __syncthreads();

    const int i = tid / 12, tag = tid % 12;   // 384 = 32*12
    float acc = bs[tag];
    #pragma unroll 8
    for (int k = 0; k < 256; k++)
        acc += hbuf[i][k] * Ws[tag][k];
    g_y[(size_t)(m0 + i) * NTAG + tag] = acc;
}

// =====================================================================
// K4: CRF forward + gold. 1 warp per batch elem.
//   exp-factorized recurrence: lse_j(sc_j + tr_lj) = M + log(sum_j e^{sc_j-M} etr_lj)
// =====================================================================
__global__ void __launch_bounds__(32) k_crf(
    const int* __restrict__ y0, const float* __restrict__ trans,
    float* __restrict__ out)
{
    const int b = blockIdx.x;
    const int lane = threadIdx.x;

    __shared__ float tr[144];
    __shared__ float sc[16];
    __shared__ float eb[16];

    for (int i = lane; i < 144; i += 32) tr[i] = trans[i];
    if (lane < 16) { sc[lane] = NEGV; eb[lane] = 0.f; }
    __syncwarp();
    if (lane == 0) sc[SOS_T] = 0.0f;

    // per-lane register copy of exp(trans[lane][:])
    float etr[12];
    #pragma unroll
    for (int jj = 0; jj < 12; jj++)
        etr[jj] = (lane < 12) ? __expf(tr[lane * 12 + jj]) : 0.f;
    __syncwarp();

    const float* __restrict__ yb = g_y + (size_t)b * SEQ * NTAG;

    float emit_next = (lane < 12) ? yb[lane] : 0.f;

    for (int t = 0; t < SEQ; t++) {
        const float4 s0 = *(const float4*)&sc[0];
        const float4 s1 = *(const float4*)&sc[4];
        const float4 s2 = *(const float4*)&sc[8];
        float M = fmaxf(fmaxf(fmaxf(s0.x, s0.y), fmaxf(s0.z, s0.w)),
                  fmaxf(fmaxf(fmaxf(s1.x, s1.y), fmaxf(s1.z, s1.w)),
                        fmaxf(fmaxf(s2.x, s2.y), fmaxf(s2.z, s2.w))));
        if (lane < 12) eb[lane] = __expf(sc[lane] - M);
        const float emit = emit_next;
        __syncwarp();

        float nv = 0.f;
        if (lane < 12) {
            const float4 e0 = *(const float4*)&eb[0];
            const float4 e1 = *(const float4*)&eb[4];
            const float4 e2 = *(const float4*)&eb[8];
            float d = e0.x * etr[0] + e0.y * etr[1] + e0.z * etr[2] + e0.w * etr[3];
            d += e1.x * etr[4] + e1.y * etr[5] + e1.z * etr[6] + e1.w * etr[7];
            d += e2.x * etr[8] + e2.y * etr[9] + e2.z * etr[10] + e2.w * etr[11];
            nv = M + __logf(d) + emit;
        }
        if (t + 1 < SEQ && lane < 12) emit_next = yb[(t + 1) * NTAG + lane];
        __syncwarp();
        if (lane < 12) sc[lane] = nv;
        __syncwarp();
    }

    // gold path: emissions + transitions along y0 path
    const int* __restrict__ y0b = y0 + b * SEQ;
    float emit = 0.f, trs = 0.f;
    for (int t = lane; t < SEQ; t += 32) {
        const int cur = y0b[t];
        const int prev = (t == 0) ? SOS_T : y0b[t - 1];
        emit += yb[t * NTAG + cur];
        trs  += tr[cur * 12 + prev];
    }
    #pragma unroll
    for (int off = 16; off > 0; off >>= 1) {
        emit += __shfl_down_sync(0xffffffffu, emit, off);
        trs  += __shfl_down_sync(0xffffffffu, trs,  off);
    }

    if (lane == 0) {
        float mx = -3.0e38f;
        #pragma unroll
        for (int jj = 0; jj < 12; jj++)
            mx = fmaxf(mx, sc[jj] + tr[EOS_T * 12 + jj]);
        float s = 0.f;
        #pragma unroll
        for (int jj = 0; jj < 12; jj++)
            s += __expf(sc[jj] + tr[EOS_T * 12 + jj] - mx);
        const float Z = mx + __logf(s);
        const float gold = emit + trs + tr[EOS_T * 12 + y0b[SEQ - 1]];
        out[b] = Z - gold;
    }
}

// =====================================================================
extern "C" void kernel_launch(void* const* d_in, const int* in_sizes, int n_in,
                              void* d_out, int out_size)
{
    (void)in_sizes; (void)n_in; (void)out_size;
    const int*   x     = (const int*)  d_in[0];
    const int*   y0    = (const int*)  d_in[1];
    const float* embed = (const float*)d_in[2];
    const float* Wih_f = (const float*)d_in[3];
    const float* Whh_f = (const float*)d_in[4];
    const float* b_f   = (const float*)d_in[5];
    const float* Wih_b = (const float*)d_in[6];
    const float* Whh_b = (const float*)d_in[7];
    const float* b_b   = (const float*)d_in[8];
    const float* Wout  = (const float*)d_in[9];
    const float* bout  = (const float*)d_in[10];
    const float* trans = (const float*)d_in[11];
    float* out = (float*)d_out;

    dim3 gwt(32, 2);
    k_wt<<<gwt, 512>>>(Whh_f, Whh_b);
    dim3 g1(4, 512, 2);
    k_input_gemm<<<g1, 256>>>(x, embed, Wih_f, b_f, Wih_b, b_b);
    k_lstm<<<64, 512>>>();
    k_proj<<<2048, 384>>>(Wout, bout);
    k_crf<<<128, 32>>>(y0, trans, out);
}